// round 4
// baseline (speedup 1.0000x reference)
#include <cuda_runtime.h>
#include <math.h>

#define Bn 64
#define Tn 512
#define Dn 256
#define Un 256

// (b*T + t, [r|z|h], u) : x@W + bias, precomputed
__device__ float g_xw[(size_t)Bn * Tn * 3 * Un];
// (b, t, u) : masked state ring buffer (st_m in the reference)
__device__ float g_buf[(size_t)Bn * Tn * Un];

__device__ __forceinline__ float sigmoidf_(float x) {
    return 1.f / (1.f + __expf(-x));
}

// ---------------------------------------------------------------------------
// Kernel 1: P = X @ [Wr | Wz | Wh] + [br | bz | bh]
// M = B*T = 32768, K = 256, N = 768 (three 256-wide groups)
// 128x128x8 tiles, 256 threads, 8x8 microtile per thread.
// ---------------------------------------------------------------------------
__global__ __launch_bounds__(256) void xw_gemm(
    const float* __restrict__ X,
    const float* __restrict__ Wr, const float* __restrict__ Wz,
    const float* __restrict__ Wh,
    const float* __restrict__ br, const float* __restrict__ bz,
    const float* __restrict__ bh)
{
    __shared__ float As[8][128];
    __shared__ float Bs[8][128];
    const int tid = threadIdx.x;
    const int m0 = blockIdx.x * 128;
    const int n0 = blockIdx.y * 128;
    const int gi = n0 >> 8;       // 0 -> Wr, 1 -> Wz, 2 -> Wh
    const int u0 = n0 & 255;
    const float* __restrict__ W  = (gi == 0) ? Wr : (gi == 1 ? Wz : Wh);
    const float* __restrict__ bb = (gi == 0) ? br : (gi == 1 ? bz : bh);

    const int arow = tid >> 1;
    const int acol = (tid & 1) * 4;
    const int brow = tid >> 5;
    const int bcol = (tid & 31) * 4;
    const int ty = tid >> 4, tx = tid & 15;

    float acc[8][8];
#pragma unroll
    for (int i = 0; i < 8; i++)
#pragma unroll
        for (int j = 0; j < 8; j++) acc[i][j] = 0.f;

    for (int k0 = 0; k0 < Dn; k0 += 8) {
        float4 a4 = *reinterpret_cast<const float4*>(
            &X[(size_t)(m0 + arow) * Dn + k0 + acol]);
        float4 b4 = *reinterpret_cast<const float4*>(
            &W[(size_t)(k0 + brow) * Un + u0 + bcol]);
        As[acol + 0][arow] = a4.x;
        As[acol + 1][arow] = a4.y;
        As[acol + 2][arow] = a4.z;
        As[acol + 3][arow] = a4.w;
        *reinterpret_cast<float4*>(&Bs[brow][bcol]) = b4;
        __syncthreads();
#pragma unroll
        for (int k = 0; k < 8; k++) {
            float4 a0 = *reinterpret_cast<const float4*>(&As[k][ty * 8]);
            float4 a1 = *reinterpret_cast<const float4*>(&As[k][ty * 8 + 4]);
            float4 b0 = *reinterpret_cast<const float4*>(&Bs[k][tx * 8]);
            float4 b1 = *reinterpret_cast<const float4*>(&Bs[k][tx * 8 + 4]);
            float av[8] = {a0.x, a0.y, a0.z, a0.w, a1.x, a1.y, a1.z, a1.w};
            float bv[8] = {b0.x, b0.y, b0.z, b0.w, b1.x, b1.y, b1.z, b1.w};
#pragma unroll
            for (int i = 0; i < 8; i++)
#pragma unroll
                for (int j = 0; j < 8; j++)
                    acc[i][j] += av[i] * bv[j];
        }
        __syncthreads();
    }
#pragma unroll
    for (int i = 0; i < 8; i++) {
        float* orow = g_xw + (size_t)(m0 + ty * 8 + i) * 768 + n0 + tx * 8;
#pragma unroll
        for (int j = 0; j < 8; j++)
            orow[j] = acc[i][j] + bb[u0 + tx * 8 + j];
    }
}

// ---------------------------------------------------------------------------
// Kernel 2: sequential recurrence. One CTA per batch element (64 CTAs).
// 256 threads: tid = rq*64 + c. Thread accumulates output columns 4c..4c+3
// over input slice i in [64*rq, 64*rq+64). Partials reduced via smem.
// ---------------------------------------------------------------------------
__global__ __launch_bounds__(256) void rnn_seq(
    const int*   __restrict__ deps,    // (T, 3)
    const int*   __restrict__ mask,    // (B, T)
    const float* __restrict__ init,    // (4, B, U)
    const float* __restrict__ Uzm,     // (U, U)
    const float* __restrict__ Urm,     // (U, U)
    const float* __restrict__ Uhm,     // (U, U)
    float*       __restrict__ out)     // outputs | last_out | last_state
{
    __shared__ float s[4][Un];
    __shared__ float hsum[Un];
    __shared__ float zv[Un];
    __shared__ float rsv[Un];
    __shared__ float rsp[4][Un];
    __shared__ float part_r[4][4][Un];   // [i-quarter][state][col]
    __shared__ float part_z[4][Un];
    __shared__ float part_h[4][Un];

    const int b   = blockIdx.x;
    const int tid = threadIdx.x;
    const int rq  = tid >> 6;      // i-quarter 0..3
    const int c   = tid & 63;
    const int j4  = c * 4;
    const int i0  = rq * 64;

    const float* __restrict__ xwb = g_xw + (size_t)b * Tn * 768;
    float* __restrict__ bufb = g_buf + (size_t)b * Tn * Un;
    const int* __restrict__ maskb = mask + b * Tn;

    for (int t = 0; t < Tn; t++) {
        // ---- phase 0: gather states into smem ----
        if (t == 0) {
#pragma unroll
            for (int k = 0; k < 4; k++)
                s[k][tid] = init[(size_t)k * Bn * Un + (size_t)b * Un + tid];
        } else {
#pragma unroll
            for (int kk = 0; kk < 3; kk++) {
                int d = deps[(t - 1) * 3 + kk];
                s[kk + 1][tid] = bufb[(size_t)d * Un + tid];
            }
            // s[0] persists from previous step's masked update
        }
        __syncthreads();
        hsum[tid] = s[0][tid] + s[1][tid] + s[2][tid] + s[3][tid];
        __syncthreads();

        const float* __restrict__ xwt = xwb + (size_t)t * 768;

        // ---- phase 1: r preacts (4 states share Ur rows) + z preact ----
        float4 ar0 = make_float4(0.f, 0.f, 0.f, 0.f);
        float4 ar1 = ar0, ar2 = ar0, ar3 = ar0, az = ar0;
        {
            const float* __restrict__ urp = Urm + (size_t)i0 * Un + j4;
            const float* __restrict__ uzp = Uzm + (size_t)i0 * Un + j4;
#pragma unroll 8
            for (int i = i0; i < i0 + 64; i++) {
                float4 wr = *reinterpret_cast<const float4*>(urp);
                float4 wz = *reinterpret_cast<const float4*>(uzp);
                urp += Un; uzp += Un;
                float hs = hsum[i];
                az.x += hs * wz.x; az.y += hs * wz.y;
                az.z += hs * wz.z; az.w += hs * wz.w;
                float s0 = s[0][i], s1 = s[1][i], s2 = s[2][i], s3 = s[3][i];
                ar0.x += s0 * wr.x; ar0.y += s0 * wr.y;
                ar0.z += s0 * wr.z; ar0.w += s0 * wr.w;
                ar1.x += s1 * wr.x; ar1.y += s1 * wr.y;
                ar1.z += s1 * wr.z; ar1.w += s1 * wr.w;
                ar2.x += s2 * wr.x; ar2.y += s2 * wr.y;
                ar2.z += s2 * wr.z; ar2.w += s2 * wr.w;
                ar3.x += s3 * wr.x; ar3.y += s3 * wr.y;
                ar3.z += s3 * wr.z; ar3.w += s3 * wr.w;
            }
        }
        *reinterpret_cast<float4*>(&part_r[rq][0][j4]) = ar0;
        *reinterpret_cast<float4*>(&part_r[rq][1][j4]) = ar1;
        *reinterpret_cast<float4*>(&part_r[rq][2][j4]) = ar2;
        *reinterpret_cast<float4*>(&part_r[rq][3][j4]) = ar3;
        *reinterpret_cast<float4*>(&part_z[rq][j4]) = az;
        __syncthreads();

        // ---- gates: thread handles state k=rq, cols j4..j4+3 for r;
        //      thread tid handles column tid for z ----
        {
            const int k = rq;
            float4 p  = *reinterpret_cast<const float4*>(&xwt[j4]);  // xWr + br
            float4 q0 = *reinterpret_cast<const float4*>(&part_r[0][k][j4]);
            float4 q1 = *reinterpret_cast<const float4*>(&part_r[1][k][j4]);
            float4 q2 = *reinterpret_cast<const float4*>(&part_r[2][k][j4]);
            float4 q3 = *reinterpret_cast<const float4*>(&part_r[3][k][j4]);
            float4 sg = *reinterpret_cast<const float4*>(&s[k][j4]);
            float4 rv;
            rv.x = sigmoidf_(p.x + q0.x + q1.x + q2.x + q3.x) * sg.x;
            rv.y = sigmoidf_(p.y + q0.y + q1.y + q2.y + q3.y) * sg.y;
            rv.z = sigmoidf_(p.z + q0.z + q1.z + q2.z + q3.z) * sg.z;
            rv.w = sigmoidf_(p.w + q0.w + q1.w + q2.w + q3.w) * sg.w;
            *reinterpret_cast<float4*>(&rsp[k][j4]) = rv;

            float zpre = xwt[256 + tid] + part_z[0][tid] + part_z[1][tid]
                       + part_z[2][tid] + part_z[3][tid];
            zv[tid] = sigmoidf_(zpre);
        }
        __syncthreads();
        rsv[tid] = rsp[0][tid] + rsp[1][tid] + rsp[2][tid] + rsp[3][tid];
        __syncthreads();

        // ---- phase 2: h_tilde preact = rs @ Uh ----
        float4 ah = make_float4(0.f, 0.f, 0.f, 0.f);
        {
            const float* __restrict__ uhp = Uhm + (size_t)i0 * Un + j4;
#pragma unroll 8
            for (int i = i0; i < i0 + 64; i++) {
                float4 wh = *reinterpret_cast<const float4*>(uhp);
                uhp += Un;
                float rv = rsv[i];
                ah.x += rv * wh.x; ah.y += rv * wh.y;
                ah.z += rv * wh.z; ah.w += rv * wh.w;
            }
        }
        *reinterpret_cast<float4*>(&part_h[rq][j4]) = ah;
        __syncthreads();

        // ---- final: h, mask, outputs, state/buffer update ----
        {
            float hpre = xwt[512 + tid] + part_h[0][tid] + part_h[1][tid]
                       + part_h[2][tid] + part_h[3][tid];
            float ht = tanhf(hpre);
            float z  = zv[tid];
            float hv = z * (hsum[tid] * 0.25f) + (1.f - z) * ht;
            int m = maskb[t];
            float ov = m ? hv : 0.f;
            out[((size_t)b * Tn + t) * Un + tid] = ov;
            // Reference: st_m = where(m, h, prev_state); the prev_state CARRY
            // starts at ZEROS (initial_states only feed the cell via the
            // where(t==0,...)), so the t==0 fallback is 0, not init[0].
            float prev = (t == 0) ? 0.f : s[0][tid];
            float st = m ? hv : prev;
            s[0][tid] = st;
            bufb[(size_t)t * Un + tid] = st;
            if (t == Tn - 1) {
                out[(size_t)Bn * Tn * Un + (size_t)b * Un + tid] = ov;  // last_out
                out[(size_t)Bn * Tn * Un + (size_t)Bn * Un
                    + (size_t)b * Un + tid] = st;                        // last_state
            }
        }
        __syncthreads();
    }
}

// ---------------------------------------------------------------------------
// Input order (metadata): 0 inputs, 1 dependencies, 2 mask, 3 initial_states,
// 4 Wz, 5 Wr, 6 Wh, 7 Uz, 8 Ur, 9 Uh, 10 bz, 11 br, 12 bh
// Output: outputs (B,T,U) | last_out (B,U) | last_state (B,U), flattened.
// ---------------------------------------------------------------------------
extern "C" void kernel_launch(void* const* d_in, const int* in_sizes, int n_in,
                              void* d_out, int out_size) {
    const float* X    = (const float*)d_in[0];
    const int*   deps = (const int*)  d_in[1];
    const int*   mask = (const int*)  d_in[2];
    const float* init = (const float*)d_in[3];
    const float* Wz   = (const float*)d_in[4];
    const float* Wr   = (const float*)d_in[5];
    const float* Wh   = (const float*)d_in[6];
    const float* Uz   = (const float*)d_in[7];
    const float* Ur   = (const float*)d_in[8];
    const float* Uh   = (const float*)d_in[9];
    const float* bz   = (const float*)d_in[10];
    const float* br   = (const float*)d_in[11];
    const float* bh   = (const float*)d_in[12];
    float* out = (float*)d_out;

    dim3 g1(256, 6);   // (32768/128, 768/128)
    xw_gemm<<<g1, 256>>>(X, Wr, Wz, Wh, br, bz, bh);
    rnn_seq<<<64, 256>>>(deps, mask, init, Uz, Ur, Uh, out);
}

// round 6
// speedup vs baseline: 2.0326x; 2.0326x over previous
#include <cuda_runtime.h>
#include <math.h>
#include <stdint.h>

#define Bn 64
#define Tn 512
#define Dn 256
#define Un 256
#define NCOL 64            // output columns owned by each CTA (Un / cluster4)

// (b*T + t, [r|z|h], u) : x@W + bias, precomputed
__device__ float g_xw[(size_t)Bn * Tn * 3 * Un];
// (b, t, u) : masked state buffer (st_m in the reference)
__device__ float g_buf[(size_t)Bn * Tn * Un];

__device__ __forceinline__ float sigmoidf_(float x) {
    return 1.f / (1.f + __expf(-x));
}

__device__ __forceinline__ uint32_t smem_u32(const void* p) {
    return (uint32_t)__cvta_generic_to_shared(p);
}
// store one float into the same smem offset of cluster CTA `rank`
__device__ __forceinline__ void dsmem_st(uint32_t laddr, int rank, float v) {
    uint32_t ra;
    asm("mapa.shared::cluster.u32 %0, %1, %2;" : "=r"(ra) : "r"(laddr), "r"(rank));
    asm volatile("st.shared::cluster.f32 [%0], %1;" :: "r"(ra), "f"(v) : "memory");
}
__device__ __forceinline__ void cluster_sync_() {
    asm volatile("barrier.cluster.arrive.aligned;" ::: "memory");
    asm volatile("barrier.cluster.wait.aligned;"   ::: "memory");
}

// ---------------------------------------------------------------------------
// Kernel 1: P = X @ [Wr | Wz | Wh] + [br | bz | bh]   (unchanged, works)
// ---------------------------------------------------------------------------
__global__ __launch_bounds__(256) void xw_gemm(
    const float* __restrict__ X,
    const float* __restrict__ Wr, const float* __restrict__ Wz,
    const float* __restrict__ Wh,
    const float* __restrict__ br, const float* __restrict__ bz,
    const float* __restrict__ bh)
{
    __shared__ float As[8][128];
    __shared__ float Bs[8][128];
    const int tid = threadIdx.x;
    const int m0 = blockIdx.x * 128;
    const int n0 = blockIdx.y * 128;
    const int gi = n0 >> 8;
    const int u0 = n0 & 255;
    const float* __restrict__ W  = (gi == 0) ? Wr : (gi == 1 ? Wz : Wh);
    const float* __restrict__ bb = (gi == 0) ? br : (gi == 1 ? bz : bh);

    const int arow = tid >> 1;
    const int acol = (tid & 1) * 4;
    const int brow = tid >> 5;
    const int bcol = (tid & 31) * 4;
    const int ty = tid >> 4, tx = tid & 15;

    float acc[8][8];
#pragma unroll
    for (int i = 0; i < 8; i++)
#pragma unroll
        for (int j = 0; j < 8; j++) acc[i][j] = 0.f;

    for (int k0 = 0; k0 < Dn; k0 += 8) {
        float4 a4 = *reinterpret_cast<const float4*>(
            &X[(size_t)(m0 + arow) * Dn + k0 + acol]);
        float4 b4 = *reinterpret_cast<const float4*>(
            &W[(size_t)(k0 + brow) * Un + u0 + bcol]);
        As[acol + 0][arow] = a4.x;
        As[acol + 1][arow] = a4.y;
        As[acol + 2][arow] = a4.z;
        As[acol + 3][arow] = a4.w;
        *reinterpret_cast<float4*>(&Bs[brow][bcol]) = b4;
        __syncthreads();
#pragma unroll
        for (int k = 0; k < 8; k++) {
            float4 a0 = *reinterpret_cast<const float4*>(&As[k][ty * 8]);
            float4 a1 = *reinterpret_cast<const float4*>(&As[k][ty * 8 + 4]);
            float4 b0 = *reinterpret_cast<const float4*>(&Bs[k][tx * 8]);
            float4 b1 = *reinterpret_cast<const float4*>(&Bs[k][tx * 8 + 4]);
            float av[8] = {a0.x, a0.y, a0.z, a0.w, a1.x, a1.y, a1.z, a1.w};
            float bv[8] = {b0.x, b0.y, b0.z, b0.w, b1.x, b1.y, b1.z, b1.w};
#pragma unroll
            for (int i = 0; i < 8; i++)
#pragma unroll
                for (int j = 0; j < 8; j++)
                    acc[i][j] += av[i] * bv[j];
        }
        __syncthreads();
    }
#pragma unroll
    for (int i = 0; i < 8; i++) {
        float* orow = g_xw + (size_t)(m0 + ty * 8 + i) * 768 + n0 + tx * 8;
#pragma unroll
        for (int j = 0; j < 8; j++)
            orow[j] = acc[i][j] + bb[u0 + tx * 8 + j];
    }
}

// ---------------------------------------------------------------------------
// Kernel 2: recurrence. 32 clusters of 4 CTAs; cluster c handles chains
// b0=2c, b1=2c+1 in lockstep (states packed float2). CTA rank owns output
// columns [64*rank, 64*rank+64); its weight slices (Ur/Uz/Uh columns) are
// SMEM-resident fp32. Cross-CTA dense vectors (rs, h) exchanged via DSMEM.
//
// smem (floats):
//   W    [3][256][64]        @0       196608 B   (0=Ur, 1=Uz, 2=Uh)
//   part [8][5][2][64]       @49152    20480 B   (phase2 reuses gate slot 0)
//   sv   [4][256][2]         @54272     8192 B   (states, packed 2 chains)
//   hs   [256][2]            @56320     2048 B
//   rs   [256][2]            @56832     2048 B
//   zb   [64][2]             @57344      512 B
// total 57472 floats = 229888 B
// ---------------------------------------------------------------------------
#define OFF_PART 49152
#define OFF_S    54272
#define OFF_HS   56320
#define OFF_RS   56832
#define OFF_Z    57344
#define SMEM_BYTES (57472 * 4)

__global__ __launch_bounds__(256, 1) __cluster_dims__(4, 1, 1)
void rnn_seq4(const int*   __restrict__ deps,    // (T, 3)
              const int*   __restrict__ mask,    // (B, T)
              const float* __restrict__ init,    // (4, B, U)
              const float* __restrict__ Uzm, const float* __restrict__ Urm,
              const float* __restrict__ Uhm,
              float*       __restrict__ out)
{
    extern __shared__ float sm[];
    float* Ws   = sm;
    float* part = sm + OFF_PART;
    float* sv   = sm + OFF_S;
    float* hs   = sm + OFF_HS;
    float* rs   = sm + OFF_RS;
    float* zb   = sm + OFF_Z;

    const int tid  = threadIdx.x;
    const int rank = blockIdx.x & 3;
    const int cl   = blockIdx.x >> 2;
    const int b0   = cl * 2, b1 = b0 + 1;
    const int col0 = rank * NCOL;

    // ---- load weight column-slices into smem (once) ----
    for (int idx = tid; idx < 256 * NCOL; idx += 256) {
        int i = idx >> 6, j = idx & 63;
        Ws[idx]          = Urm[i * Un + col0 + j];
        Ws[16384 + idx]  = Uzm[i * Un + col0 + j];
        Ws[32768 + idx]  = Uhm[i * Un + col0 + j];
    }
    __syncthreads();

    const int sl = tid >> 4;          // i-slice 0..15 (16 rows each)
    const int j0 = (tid & 15) * 4;    // 4 local columns

    for (int t = 0; t < Tn; t++) {
        // ---- gather states (packed chains) ----
        if (t == 0) {
#pragma unroll
            for (int k = 0; k < 4; k++) {
                sv[(k * 256 + tid) * 2 + 0] = init[((size_t)k * Bn + b0) * Un + tid];
                sv[(k * 256 + tid) * 2 + 1] = init[((size_t)k * Bn + b1) * Un + tid];
            }
        } else {
#pragma unroll
            for (int k = 1; k < 4; k++) {
                int d = deps[(t - 1) * 3 + (k - 1)];
                sv[(k * 256 + tid) * 2 + 0] = g_buf[((size_t)b0 * Tn + d) * Un + tid];
                sv[(k * 256 + tid) * 2 + 1] = g_buf[((size_t)b1 * Tn + d) * Un + tid];
            }
            // sv[0] holds the carried masked state (updated via DSMEM below)
        }
        __syncthreads();
        {
            float2 h2;
            h2.x = sv[(0*256+tid)*2] + sv[(1*256+tid)*2] + sv[(2*256+tid)*2] + sv[(3*256+tid)*2];
            h2.y = sv[(0*256+tid)*2+1] + sv[(1*256+tid)*2+1] + sv[(2*256+tid)*2+1] + sv[(3*256+tid)*2+1];
            hs[tid*2] = h2.x; hs[tid*2+1] = h2.y;
        }
        __syncthreads();

        // ---- phase 1: r preacts (4 states) + z preact over 16-row slice ----
        float2 accR[4][4];      // [state][col]
        float2 accZ[4];
#pragma unroll
        for (int k = 0; k < 4; k++)
#pragma unroll
            for (int c = 0; c < 4; c++) accR[k][c] = make_float2(0.f, 0.f);
#pragma unroll
        for (int c = 0; c < 4; c++) accZ[c] = make_float2(0.f, 0.f);

#pragma unroll
        for (int rr = 0; rr < 16; rr++) {
            const int i = (sl << 4) + rr;
            const float4 wr = *reinterpret_cast<const float4*>(&Ws[(i << 6) + j0]);
            const float4 wz = *reinterpret_cast<const float4*>(&Ws[16384 + (i << 6) + j0]);
            const float2 s0 = *reinterpret_cast<const float2*>(&sv[(0*256 + i) * 2]);
            const float2 s1 = *reinterpret_cast<const float2*>(&sv[(1*256 + i) * 2]);
            const float2 s2 = *reinterpret_cast<const float2*>(&sv[(2*256 + i) * 2]);
            const float2 s3 = *reinterpret_cast<const float2*>(&sv[(3*256 + i) * 2]);
            const float2 hp = *reinterpret_cast<const float2*>(&hs[i * 2]);
            const float wa[4] = {wr.x, wr.y, wr.z, wr.w};
            const float za[4] = {wz.x, wz.y, wz.z, wz.w};
#pragma unroll
            for (int c = 0; c < 4; c++) {
                accR[0][c].x += wa[c] * s0.x;  accR[0][c].y += wa[c] * s0.y;
                accR[1][c].x += wa[c] * s1.x;  accR[1][c].y += wa[c] * s1.y;
                accR[2][c].x += wa[c] * s2.x;  accR[2][c].y += wa[c] * s2.y;
                accR[3][c].x += wa[c] * s3.x;  accR[3][c].y += wa[c] * s3.y;
                accZ[c].x   += za[c] * hp.x;   accZ[c].y   += za[c] * hp.y;
            }
        }
        // combine slice pairs within the warp (lanes differ in bit 4 = slice)
#pragma unroll
        for (int k = 0; k < 4; k++)
#pragma unroll
            for (int c = 0; c < 4; c++) {
                accR[k][c].x += __shfl_xor_sync(0xffffffffu, accR[k][c].x, 16);
                accR[k][c].y += __shfl_xor_sync(0xffffffffu, accR[k][c].y, 16);
            }
#pragma unroll
        for (int c = 0; c < 4; c++) {
            accZ[c].x += __shfl_xor_sync(0xffffffffu, accZ[c].x, 16);
            accZ[c].y += __shfl_xor_sync(0xffffffffu, accZ[c].y, 16);
        }
        if (!(sl & 1)) {
            const int p = sl >> 1;
#pragma unroll
            for (int g = 0; g < 4; g++) {
                *reinterpret_cast<float4*>(&part[((p*5+g)*2 + 0) * 64 + j0]) =
                    make_float4(accR[g][0].x, accR[g][1].x, accR[g][2].x, accR[g][3].x);
                *reinterpret_cast<float4*>(&part[((p*5+g)*2 + 1) * 64 + j0]) =
                    make_float4(accR[g][0].y, accR[g][1].y, accR[g][2].y, accR[g][3].y);
            }
            *reinterpret_cast<float4*>(&part[((p*5+4)*2 + 0) * 64 + j0]) =
                make_float4(accZ[0].x, accZ[1].x, accZ[2].x, accZ[3].x);
            *reinterpret_cast<float4*>(&part[((p*5+4)*2 + 1) * 64 + j0]) =
                make_float4(accZ[0].y, accZ[1].y, accZ[2].y, accZ[3].y);
        }
        __syncthreads();

        // ---- gate stage: r_k, rs, z for this CTA's 64 cols (2 chains) ----
        if (tid < 128) {
            const int ch = tid >> 6, j = tid & 63;
            const int bb = ch ? b1 : b0;
            const float* xwrow = g_xw + ((size_t)bb * Tn + t) * 768;
            float pr[5] = {0.f, 0.f, 0.f, 0.f, 0.f};
#pragma unroll
            for (int p = 0; p < 8; p++)
#pragma unroll
                for (int g = 0; g < 5; g++)
                    pr[g] += part[((p*5+g)*2 + ch) * 64 + j];
            const float xr = xwrow[col0 + j];
            float rsum = 0.f;
#pragma unroll
            for (int k = 0; k < 4; k++) {
                float rg = sigmoidf_(xr + pr[k]);
                rsum += rg * sv[(k * 256 + col0 + j) * 2 + ch];
            }
            zb[j * 2 + ch] = sigmoidf_(xwrow[256 + col0 + j] + pr[4]);
            const uint32_t la = smem_u32(&rs[(col0 + j) * 2 + ch]);
#pragma unroll
            for (int r4 = 0; r4 < 4; r4++) dsmem_st(la, r4, rsum);
        }
        cluster_sync_();

        // ---- phase 2: h_tilde preact = rs @ Uh (slice) ----
        float2 acc2[4];
#pragma unroll
        for (int c = 0; c < 4; c++) acc2[c] = make_float2(0.f, 0.f);
#pragma unroll
        for (int rr = 0; rr < 16; rr++) {
            const int i = (sl << 4) + rr;
            const float4 wh = *reinterpret_cast<const float4*>(&Ws[32768 + (i << 6) + j0]);
            const float2 rp = *reinterpret_cast<const float2*>(&rs[i * 2]);
            const float wa[4] = {wh.x, wh.y, wh.z, wh.w};
#pragma unroll
            for (int c = 0; c < 4; c++) {
                acc2[c].x += wa[c] * rp.x;
                acc2[c].y += wa[c] * rp.y;
            }
        }
#pragma unroll
        for (int c = 0; c < 4; c++) {
            acc2[c].x += __shfl_xor_sync(0xffffffffu, acc2[c].x, 16);
            acc2[c].y += __shfl_xor_sync(0xffffffffu, acc2[c].y, 16);
        }
        if (!(sl & 1)) {
            const int p = sl >> 1;       // reuse gate-0 slots of part
            *reinterpret_cast<float4*>(&part[((p*5)*2 + 0) * 64 + j0]) =
                make_float4(acc2[0].x, acc2[1].x, acc2[2].x, acc2[3].x);
            *reinterpret_cast<float4*>(&part[((p*5)*2 + 1) * 64 + j0]) =
                make_float4(acc2[0].y, acc2[1].y, acc2[2].y, acc2[3].y);
        }
        __syncthreads();

        // ---- final: h, mask, outputs, push new state to all ranks ----
        if (tid < 128) {
            const int ch = tid >> 6, j = tid & 63;
            const int bb = ch ? b1 : b0;
            const int col = col0 + j;
            float ph = 0.f;
#pragma unroll
            for (int p = 0; p < 8; p++) ph += part[((p*5)*2 + ch) * 64 + j];
            const float xh = g_xw[((size_t)bb * Tn + t) * 768 + 512 + col];
            const float ht = tanhf(xh + ph);
            const float z  = zb[j * 2 + ch];
            const float h  = z * hs[col * 2 + ch] * 0.25f + (1.f - z) * ht;
            const int m = mask[bb * Tn + t];
            const float ov = m ? h : 0.f;
            out[((size_t)bb * Tn + t) * Un + col] = ov;
            const float prev = (t == 0) ? 0.f : sv[(0 * 256 + col) * 2 + ch];
            const float st = m ? h : prev;
            const uint32_t la = smem_u32(&sv[(0 * 256 + col) * 2 + ch]);
#pragma unroll
            for (int r4 = 0; r4 < 4; r4++) dsmem_st(la, r4, st);
            if (t == Tn - 1) {
                out[(size_t)Bn * Tn * Un + (size_t)bb * Un + col] = ov;
                out[(size_t)Bn * Tn * Un + (size_t)Bn * Un + (size_t)bb * Un + col] = st;
            }
        }
        cluster_sync_();

        // every CTA writes the full buf row itself (reads own writes later,
        // so no cross-CTA global visibility is needed)
        g_buf[((size_t)b0 * Tn + t) * Un + tid] = sv[tid * 2];
        g_buf[((size_t)b1 * Tn + t) * Un + tid] = sv[tid * 2 + 1];
        __syncthreads();
    }
}

// ---------------------------------------------------------------------------
// Inputs: 0 inputs, 1 dependencies, 2 mask, 3 initial_states,
// 4 Wz, 5 Wr, 6 Wh, 7 Uz, 8 Ur, 9 Uh, 10 bz, 11 br, 12 bh
// ---------------------------------------------------------------------------
extern "C" void kernel_launch(void* const* d_in, const int* in_sizes, int n_in,
                              void* d_out, int out_size) {
    const float* X    = (const float*)d_in[0];
    const int*   deps = (const int*)  d_in[1];
    const int*   mask = (const int*)  d_in[2];
    const float* init = (const float*)d_in[3];
    const float* Wz   = (const float*)d_in[4];
    const float* Wr   = (const float*)d_in[5];
    const float* Wh   = (const float*)d_in[6];
    const float* Uz   = (const float*)d_in[7];
    const float* Ur   = (const float*)d_in[8];
    const float* Uh   = (const float*)d_in[9];
    const float* bz   = (const float*)d_in[10];
    const float* br   = (const float*)d_in[11];
    const float* bh   = (const float*)d_in[12];
    float* out = (float*)d_out;

    cudaFuncSetAttribute(rnn_seq4, cudaFuncAttributeMaxDynamicSharedMemorySize,
                         SMEM_BYTES);

    dim3 g1(256, 6);   // (32768/128, 768/128)
    xw_gemm<<<g1, 256>>>(X, Wr, Wz, Wh, br, bz, bh);
    rnn_seq4<<<128, 256, SMEM_BYTES>>>(deps, mask, init, Uz, Ur, Uh, out);
}

// round 7
// speedup vs baseline: 2.1283x; 1.0471x over previous
#include <cuda_runtime.h>
#include <math.h>
#include <stdint.h>

#define Bn 64
#define Tn 512
#define Dn 256
#define Un 256
#define NCOL 64            // output columns owned by each CTA (Un / cluster4)

// (b*T + t, [r|z|h], u) : x@W + bias, precomputed
__device__ float g_xw[(size_t)Bn * Tn * 3 * Un];
// (b, t, u) : masked state buffer (st_m in the reference)
__device__ float g_buf[(size_t)Bn * Tn * Un];

__device__ __forceinline__ float sigmoidf_(float x) {
    return 1.f / (1.f + __expf(-x));
}

__device__ __forceinline__ uint32_t smem_u32(const void* p) {
    return (uint32_t)__cvta_generic_to_shared(p);
}
__device__ __forceinline__ void dsmem_st(uint32_t laddr, int rank, float v) {
    uint32_t ra;
    asm("mapa.shared::cluster.u32 %0, %1, %2;" : "=r"(ra) : "r"(laddr), "r"(rank));
    asm volatile("st.shared::cluster.f32 [%0], %1;" :: "r"(ra), "f"(v) : "memory");
}
__device__ __forceinline__ void cluster_sync_() {
    asm volatile("barrier.cluster.arrive.aligned;" ::: "memory");
    asm volatile("barrier.cluster.wait.aligned;"   ::: "memory");
}

// ---- packed f32x2 helpers (chains packed in low/high halves) ----
typedef unsigned long long u64;
__device__ __forceinline__ u64 pack2(float a) {            // {a, a}
    u64 r; asm("mov.b64 %0, {%1, %1};" : "=l"(r) : "f"(a)); return r;
}
__device__ __forceinline__ u64 ffma2(u64 a, u64 b, u64 c) {
    u64 d; asm("fma.rn.f32x2 %0, %1, %2, %3;" : "=l"(d) : "l"(a), "l"(b), "l"(c));
    return d;
}
__device__ __forceinline__ u64 fadd2(u64 a, u64 b) {
    u64 d; asm("add.rn.f32x2 %0, %1, %2;" : "=l"(d) : "l"(a), "l"(b));
    return d;
}
__device__ __forceinline__ float2 u2f(u64 v) {
    float2 r; asm("mov.b64 {%0, %1}, %2;" : "=f"(r.x), "=f"(r.y) : "l"(v));
    return r;
}

// ---------------------------------------------------------------------------
// Kernel 1: P = X @ [Wr | Wz | Wh] + [br | bz | bh]   (unchanged)
// ---------------------------------------------------------------------------
__global__ __launch_bounds__(256) void xw_gemm(
    const float* __restrict__ X,
    const float* __restrict__ Wr, const float* __restrict__ Wz,
    const float* __restrict__ Wh,
    const float* __restrict__ br, const float* __restrict__ bz,
    const float* __restrict__ bh)
{
    __shared__ float As[8][128];
    __shared__ float Bs[8][128];
    const int tid = threadIdx.x;
    const int m0 = blockIdx.x * 128;
    const int n0 = blockIdx.y * 128;
    const int gi = n0 >> 8;
    const int u0 = n0 & 255;
    const float* __restrict__ W  = (gi == 0) ? Wr : (gi == 1 ? Wz : Wh);
    const float* __restrict__ bb = (gi == 0) ? br : (gi == 1 ? bz : bh);

    const int arow = tid >> 1;
    const int acol = (tid & 1) * 4;
    const int brow = tid >> 5;
    const int bcol = (tid & 31) * 4;
    const int ty = tid >> 4, tx = tid & 15;

    float acc[8][8];
#pragma unroll
    for (int i = 0; i < 8; i++)
#pragma unroll
        for (int j = 0; j < 8; j++) acc[i][j] = 0.f;

    for (int k0 = 0; k0 < Dn; k0 += 8) {
        float4 a4 = *reinterpret_cast<const float4*>(
            &X[(size_t)(m0 + arow) * Dn + k0 + acol]);
        float4 b4 = *reinterpret_cast<const float4*>(
            &W[(size_t)(k0 + brow) * Un + u0 + bcol]);
        As[acol + 0][arow] = a4.x;
        As[acol + 1][arow] = a4.y;
        As[acol + 2][arow] = a4.z;
        As[acol + 3][arow] = a4.w;
        *reinterpret_cast<float4*>(&Bs[brow][bcol]) = b4;
        __syncthreads();
#pragma unroll
        for (int k = 0; k < 8; k++) {
            float4 a0 = *reinterpret_cast<const float4*>(&As[k][ty * 8]);
            float4 a1 = *reinterpret_cast<const float4*>(&As[k][ty * 8 + 4]);
            float4 b0 = *reinterpret_cast<const float4*>(&Bs[k][tx * 8]);
            float4 b1 = *reinterpret_cast<const float4*>(&Bs[k][tx * 8 + 4]);
            float av[8] = {a0.x, a0.y, a0.z, a0.w, a1.x, a1.y, a1.z, a1.w};
            float bv[8] = {b0.x, b0.y, b0.z, b0.w, b1.x, b1.y, b1.z, b1.w};
#pragma unroll
            for (int i = 0; i < 8; i++)
#pragma unroll
                for (int j = 0; j < 8; j++)
                    acc[i][j] += av[i] * bv[j];
        }
        __syncthreads();
    }
#pragma unroll
    for (int i = 0; i < 8; i++) {
        float* orow = g_xw + (size_t)(m0 + ty * 8 + i) * 768 + n0 + tx * 8;
#pragma unroll
        for (int j = 0; j < 8; j++)
            orow[j] = acc[i][j] + bb[u0 + tx * 8 + j];
    }
}

// ---------------------------------------------------------------------------
// Kernel 2: recurrence. 32 clusters x 4 CTAs; 2 chains per cluster packed
// as f32x2. Weight column-slices SMEM-resident. FFMA2 inner loops.
//
// smem (floats):
//   W    [3][256][64]     @0       196608 B  (0=Ur, 1=Uz, 2=Uh)
//   part [8][5][2][64]    @49152    20480 B  (phase2 reuses gate slot 0)
//   sv   [4][256][2]      @54272     8192 B
//   rs   [256][2]         @56320     2048 B
//   zb   [64][2]          @56832      512 B
// total 56960 floats = 227840 B
// ---------------------------------------------------------------------------
#define OFF_PART 49152
#define OFF_S    54272
#define OFF_RS   56320
#define OFF_Z    56832
#define SMEM_BYTES (56960 * 4)

__global__ __launch_bounds__(256, 1) __cluster_dims__(4, 1, 1)
void rnn_seq4(const int*   __restrict__ deps,    // (T, 3)
              const int*   __restrict__ mask,    // (B, T)
              const float* __restrict__ init,    // (4, B, U)
              const float* __restrict__ Uzm, const float* __restrict__ Urm,
              const float* __restrict__ Uhm,
              float*       __restrict__ out)
{
    extern __shared__ float sm[];
    float* Ws   = sm;
    float* part = sm + OFF_PART;
    float* sv   = sm + OFF_S;
    float* rs   = sm + OFF_RS;
    float* zb   = sm + OFF_Z;

    const int tid  = threadIdx.x;
    const int rank = blockIdx.x & 3;
    const int cl   = blockIdx.x >> 2;
    const int b0   = cl * 2, b1 = b0 + 1;
    const int col0 = rank * NCOL;

    // ---- load weight column-slices into smem (once) ----
    for (int idx = tid; idx < 256 * NCOL; idx += 256) {
        int i = idx >> 6, j = idx & 63;
        Ws[idx]          = Urm[i * Un + col0 + j];
        Ws[16384 + idx]  = Uzm[i * Un + col0 + j];
        Ws[32768 + idx]  = Uhm[i * Un + col0 + j];
    }
    __syncthreads();

    const int sl = tid >> 4;          // i-slice 0..15 (16 rows each)
    const int j0 = (tid & 15) * 4;    // 4 local columns

    for (int t = 0; t < Tn; t++) {
        // ---- gather states (packed chains) ----
        if (t == 0) {
#pragma unroll
            for (int k = 0; k < 4; k++) {
                sv[(k * 256 + tid) * 2 + 0] = init[((size_t)k * Bn + b0) * Un + tid];
                sv[(k * 256 + tid) * 2 + 1] = init[((size_t)k * Bn + b1) * Un + tid];
            }
        } else {
#pragma unroll
            for (int k = 1; k < 4; k++) {
                int d = deps[(t - 1) * 3 + (k - 1)];
                sv[(k * 256 + tid) * 2 + 0] = g_buf[((size_t)b0 * Tn + d) * Un + tid];
                sv[(k * 256 + tid) * 2 + 1] = g_buf[((size_t)b1 * Tn + d) * Un + tid];
            }
            // sv[0] holds the carried masked state (pushed via DSMEM below)
        }
        __syncthreads();

        // ---- phase 1: r preacts (4 states) + z preact, packed f32x2 ----
        u64 accR[4][4];     // [state][col]
        u64 accZ[4];
#pragma unroll
        for (int k = 0; k < 4; k++)
#pragma unroll
            for (int c = 0; c < 4; c++) accR[k][c] = 0ull;
#pragma unroll
        for (int c = 0; c < 4; c++) accZ[c] = 0ull;

#pragma unroll
        for (int rr = 0; rr < 16; rr++) {
            const int i = (sl << 4) + rr;
            const float4 wr = *reinterpret_cast<const float4*>(&Ws[(i << 6) + j0]);
            const float4 wz = *reinterpret_cast<const float4*>(&Ws[16384 + (i << 6) + j0]);
            const u64 s0 = *reinterpret_cast<const u64*>(&sv[(0*256 + i) * 2]);
            const u64 s1 = *reinterpret_cast<const u64*>(&sv[(1*256 + i) * 2]);
            const u64 s2 = *reinterpret_cast<const u64*>(&sv[(2*256 + i) * 2]);
            const u64 s3 = *reinterpret_cast<const u64*>(&sv[(3*256 + i) * 2]);
            const u64 hp = fadd2(fadd2(s0, s1), fadd2(s2, s3));
            const u64 w0 = pack2(wr.x), w1 = pack2(wr.y),
                      w2 = pack2(wr.z), w3 = pack2(wr.w);
            const u64 z0 = pack2(wz.x), z1 = pack2(wz.y),
                      z2 = pack2(wz.z), z3 = pack2(wz.w);
            accR[0][0] = ffma2(w0, s0, accR[0][0]);
            accR[0][1] = ffma2(w1, s0, accR[0][1]);
            accR[0][2] = ffma2(w2, s0, accR[0][2]);
            accR[0][3] = ffma2(w3, s0, accR[0][3]);
            accR[1][0] = ffma2(w0, s1, accR[1][0]);
            accR[1][1] = ffma2(w1, s1, accR[1][1]);
            accR[1][2] = ffma2(w2, s1, accR[1][2]);
            accR[1][3] = ffma2(w3, s1, accR[1][3]);
            accR[2][0] = ffma2(w0, s2, accR[2][0]);
            accR[2][1] = ffma2(w1, s2, accR[2][1]);
            accR[2][2] = ffma2(w2, s2, accR[2][2]);
            accR[2][3] = ffma2(w3, s2, accR[2][3]);
            accR[3][0] = ffma2(w0, s3, accR[3][0]);
            accR[3][1] = ffma2(w1, s3, accR[3][1]);
            accR[3][2] = ffma2(w2, s3, accR[3][2]);
            accR[3][3] = ffma2(w3, s3, accR[3][3]);
            accZ[0] = ffma2(z0, hp, accZ[0]);
            accZ[1] = ffma2(z1, hp, accZ[1]);
            accZ[2] = ffma2(z2, hp, accZ[2]);
            accZ[3] = ffma2(z3, hp, accZ[3]);
        }
        // combine slice pairs within the warp (lanes differ in bit 4)
#pragma unroll
        for (int k = 0; k < 4; k++)
#pragma unroll
            for (int c = 0; c < 4; c++)
                accR[k][c] = fadd2(accR[k][c],
                    __shfl_xor_sync(0xffffffffu, accR[k][c], 16));
#pragma unroll
        for (int c = 0; c < 4; c++)
            accZ[c] = fadd2(accZ[c],
                __shfl_xor_sync(0xffffffffu, accZ[c], 16));
        if (!(sl & 1)) {
            const int p = sl >> 1;
#pragma unroll
            for (int g = 0; g < 4; g++) {
                float2 a0 = u2f(accR[g][0]), a1 = u2f(accR[g][1]);
                float2 a2 = u2f(accR[g][2]), a3 = u2f(accR[g][3]);
                *reinterpret_cast<float4*>(&part[((p*5+g)*2 + 0) * 64 + j0]) =
                    make_float4(a0.x, a1.x, a2.x, a3.x);
                *reinterpret_cast<float4*>(&part[((p*5+g)*2 + 1) * 64 + j0]) =
                    make_float4(a0.y, a1.y, a2.y, a3.y);
            }
            float2 c0 = u2f(accZ[0]), c1 = u2f(accZ[1]);
            float2 c2 = u2f(accZ[2]), c3 = u2f(accZ[3]);
            *reinterpret_cast<float4*>(&part[((p*5+4)*2 + 0) * 64 + j0]) =
                make_float4(c0.x, c1.x, c2.x, c3.x);
            *reinterpret_cast<float4*>(&part[((p*5+4)*2 + 1) * 64 + j0]) =
                make_float4(c0.y, c1.y, c2.y, c3.y);
        }
        __syncthreads();

        // ---- gate stage: r_k, rs, z for this CTA's 64 cols (2 chains) ----
        if (tid < 128) {
            const int ch = tid >> 6, j = tid & 63;
            const int bb = ch ? b1 : b0;
            const float* xwrow = g_xw + ((size_t)bb * Tn + t) * 768;
            float pr[5] = {0.f, 0.f, 0.f, 0.f, 0.f};
#pragma unroll
            for (int p = 0; p < 8; p++)
#pragma unroll
                for (int g = 0; g < 5; g++)
                    pr[g] += part[((p*5+g)*2 + ch) * 64 + j];
            const float xr = xwrow[col0 + j];
            float rsum = 0.f;
#pragma unroll
            for (int k = 0; k < 4; k++) {
                float rg = sigmoidf_(xr + pr[k]);
                rsum += rg * sv[(k * 256 + col0 + j) * 2 + ch];
            }
            zb[j * 2 + ch] = sigmoidf_(xwrow[256 + col0 + j] + pr[4]);
            const uint32_t la = smem_u32(&rs[(col0 + j) * 2 + ch]);
#pragma unroll
            for (int r4 = 0; r4 < 4; r4++) dsmem_st(la, r4, rsum);
        }
        cluster_sync_();

        // ---- phase 2: h_tilde preact = rs @ Uh, packed f32x2 ----
        u64 acc2[4];
#pragma unroll
        for (int c = 0; c < 4; c++) acc2[c] = 0ull;
#pragma unroll
        for (int rr = 0; rr < 16; rr++) {
            const int i = (sl << 4) + rr;
            const float4 wh = *reinterpret_cast<const float4*>(&Ws[32768 + (i << 6) + j0]);
            const u64 rp = *reinterpret_cast<const u64*>(&rs[i * 2]);
            acc2[0] = ffma2(pack2(wh.x), rp, acc2[0]);
            acc2[1] = ffma2(pack2(wh.y), rp, acc2[1]);
            acc2[2] = ffma2(pack2(wh.z), rp, acc2[2]);
            acc2[3] = ffma2(pack2(wh.w), rp, acc2[3]);
        }
#pragma unroll
        for (int c = 0; c < 4; c++)
            acc2[c] = fadd2(acc2[c],
                __shfl_xor_sync(0xffffffffu, acc2[c], 16));
        if (!(sl & 1)) {
            const int p = sl >> 1;       // reuse gate-0 slots of part
            float2 a0 = u2f(acc2[0]), a1 = u2f(acc2[1]);
            float2 a2 = u2f(acc2[2]), a3 = u2f(acc2[3]);
            *reinterpret_cast<float4*>(&part[((p*5)*2 + 0) * 64 + j0]) =
                make_float4(a0.x, a1.x, a2.x, a3.x);
            *reinterpret_cast<float4*>(&part[((p*5)*2 + 1) * 64 + j0]) =
                make_float4(a0.y, a1.y, a2.y, a3.y);
        }
        __syncthreads();

        // ---- final: h, mask, outputs, push new state to all ranks ----
        if (tid < 128) {
            const int ch = tid >> 6, j = tid & 63;
            const int bb = ch ? b1 : b0;
            const int col = col0 + j;
            float ph = 0.f;
#pragma unroll
            for (int p = 0; p < 8; p++) ph += part[((p*5)*2 + ch) * 64 + j];
            float hsum = sv[(0*256 + col) * 2 + ch] + sv[(1*256 + col) * 2 + ch]
                       + sv[(2*256 + col) * 2 + ch] + sv[(3*256 + col) * 2 + ch];
            const float xh = g_xw[((size_t)bb * Tn + t) * 768 + 512 + col];
            const float ht = tanhf(xh + ph);
            const float z  = zb[j * 2 + ch];
            const float h  = z * hsum * 0.25f + (1.f - z) * ht;
            const int m = mask[bb * Tn + t];
            const float ov = m ? h : 0.f;
            out[((size_t)bb * Tn + t) * Un + col] = ov;
            const float prev = (t == 0) ? 0.f : sv[(0 * 256 + col) * 2 + ch];
            const float st = m ? h : prev;
            const uint32_t la = smem_u32(&sv[(0 * 256 + col) * 2 + ch]);
#pragma unroll
            for (int r4 = 0; r4 < 4; r4++) dsmem_st(la, r4, st);
            if (t == Tn - 1) {
                out[(size_t)Bn * Tn * Un + (size_t)bb * Un + col] = ov;
                out[(size_t)Bn * Tn * Un + (size_t)Bn * Un + (size_t)bb * Un + col] = st;
            }
        }
        cluster_sync_();

        // each CTA writes full buf rows itself; thread tid later re-reads only
        // element index tid, so no extra sync needed.
        g_buf[((size_t)b0 * Tn + t) * Un + tid] = sv[tid * 2];
        g_buf[((size_t)b1 * Tn + t) * Un + tid] = sv[tid * 2 + 1];
    }
}

// ---------------------------------------------------------------------------
// Inputs: 0 inputs, 1 dependencies, 2 mask, 3 initial_states,
// 4 Wz, 5 Wr, 6 Wh, 7 Uz, 8 Ur, 9 Uh, 10 bz, 11 br, 12 bh
// ---------------------------------------------------------------------------
extern "C" void kernel_launch(void* const* d_in, const int* in_sizes, int n_in,
                              void* d_out, int out_size) {
    const float* X    = (const float*)d_in[0];
    const int*   deps = (const int*)  d_in[1];
    const int*   mask = (const int*)  d_in[2];
    const float* init = (const float*)d_in[3];
    const float* Wz   = (const float*)d_in[4];
    const float* Wr   = (const float*)d_in[5];
    const float* Wh   = (const float*)d_in[6];
    const float* Uz   = (const float*)d_in[7];
    const float* Ur   = (const float*)d_in[8];
    const float* Uh   = (const float*)d_in[9];
    const float* bz   = (const float*)d_in[10];
    const float* br   = (const float*)d_in[11];
    const float* bh   = (const float*)d_in[12];
    float* out = (float*)d_out;

    cudaFuncSetAttribute(rnn_seq4, cudaFuncAttributeMaxDynamicSharedMemorySize,
                         SMEM_BYTES);

    dim3 g1(256, 6);   // (32768/128, 768/128)
    xw_gemm<<<g1, 256>>>(X, Wr, Wz, Wh, br, bz, bh);
    rnn_seq4<<<128, 256, SMEM_BYTES>>>(deps, mask, init, Uz, Ur, Uh, out);
}

// round 8
// speedup vs baseline: 3.1504x; 1.4803x over previous
#include <cuda_runtime.h>
#include <math.h>
#include <stdint.h>

#define Bn 64
#define Tn 512
#define Dn 256
#define Un 256
#define NCOL 64            // output columns owned by each CTA (Un / cluster4)

// (b*T + t, [r|z|h], u) : x@W + bias, precomputed
__device__ float g_xw[(size_t)Bn * Tn * 3 * Un];
// (cluster, t, u, ch) : masked state buffer, 2 chains packed
__device__ float g_buf[(size_t)(Bn / 2) * Tn * Un * 2];

__device__ __forceinline__ float sigmoidf_(float x) {
    return 1.f / (1.f + __expf(-x));
}
__device__ __forceinline__ uint32_t smem_u32(const void* p) {
    return (uint32_t)__cvta_generic_to_shared(p);
}
__device__ __forceinline__ void cluster_sync_() {
    asm volatile("barrier.cluster.arrive.aligned;" ::: "memory");
    asm volatile("barrier.cluster.wait.aligned;"   ::: "memory");
}
__device__ __forceinline__ void mbar_init(uint32_t bar, uint32_t cnt) {
    asm volatile("mbarrier.init.shared.b64 [%0], %1;" :: "r"(bar), "r"(cnt) : "memory");
}
__device__ __forceinline__ void mbar_expect_tx(uint32_t bar, uint32_t bytes) {
    asm volatile("mbarrier.arrive.expect_tx.shared.b64 _, [%0], %1;"
                 :: "r"(bar), "r"(bytes) : "memory");
}
__device__ __forceinline__ void mbar_wait(uint32_t bar, uint32_t parity) {
    asm volatile(
        "{\n\t.reg .pred P;\n\t"
        "W_%=:\n\t"
        "mbarrier.try_wait.parity.acquire.cta.shared::cta.b64 P, [%0], %1, 0x989680;\n\t"
        "@!P bra W_%=;\n\t"
        "}" :: "r"(bar), "r"(parity) : "memory");
}
// async store of one f32 to cluster CTA `rank`'s smem, completing on its mbarrier
__device__ __forceinline__ void st_async_f32(uint32_t daddr, uint32_t baddr,
                                             int rank, float v) {
    uint32_t ra, rb;
    asm("mapa.shared::cluster.u32 %0, %1, %2;" : "=r"(ra) : "r"(daddr), "r"(rank));
    asm("mapa.shared::cluster.u32 %0, %1, %2;" : "=r"(rb) : "r"(baddr), "r"(rank));
    asm volatile(
        "st.async.shared::cluster.mbarrier::complete_tx::bytes.b32 [%0], %1, [%2];"
        :: "r"(ra), "r"(__float_as_uint(v)), "r"(rb) : "memory");
}

// ---- packed f32x2 helpers (2 chains in low/high halves) ----
typedef unsigned long long u64;
__device__ __forceinline__ u64 pack2(float a) {
    u64 r; asm("mov.b64 %0, {%1, %1};" : "=l"(r) : "f"(a)); return r;
}
__device__ __forceinline__ u64 ffma2(u64 a, u64 b, u64 c) {
    u64 d; asm("fma.rn.f32x2 %0, %1, %2, %3;" : "=l"(d) : "l"(a), "l"(b), "l"(c));
    return d;
}
__device__ __forceinline__ u64 fadd2(u64 a, u64 b) {
    u64 d; asm("add.rn.f32x2 %0, %1, %2;" : "=l"(d) : "l"(a), "l"(b));
    return d;
}
__device__ __forceinline__ float2 u2f(u64 v) {
    float2 r; asm("mov.b64 {%0, %1}, %2;" : "=f"(r.x), "=f"(r.y) : "l"(v));
    return r;
}

// ---------------------------------------------------------------------------
// Kernel 1: P = X @ [Wr | Wz | Wh] + [br | bz | bh]   (unchanged)
// ---------------------------------------------------------------------------
__global__ __launch_bounds__(256) void xw_gemm(
    const float* __restrict__ X,
    const float* __restrict__ Wr, const float* __restrict__ Wz,
    const float* __restrict__ Wh,
    const float* __restrict__ br, const float* __restrict__ bz,
    const float* __restrict__ bh)
{
    __shared__ float As[8][128];
    __shared__ float Bs[8][128];
    const int tid = threadIdx.x;
    const int m0 = blockIdx.x * 128;
    const int n0 = blockIdx.y * 128;
    const int gi = n0 >> 8;
    const int u0 = n0 & 255;
    const float* __restrict__ W  = (gi == 0) ? Wr : (gi == 1 ? Wz : Wh);
    const float* __restrict__ bb = (gi == 0) ? br : (gi == 1 ? bz : bh);

    const int arow = tid >> 1;
    const int acol = (tid & 1) * 4;
    const int brow = tid >> 5;
    const int bcol = (tid & 31) * 4;
    const int ty = tid >> 4, tx = tid & 15;

    float acc[8][8];
#pragma unroll
    for (int i = 0; i < 8; i++)
#pragma unroll
        for (int j = 0; j < 8; j++) acc[i][j] = 0.f;

    for (int k0 = 0; k0 < Dn; k0 += 8) {
        float4 a4 = *reinterpret_cast<const float4*>(
            &X[(size_t)(m0 + arow) * Dn + k0 + acol]);
        float4 b4 = *reinterpret_cast<const float4*>(
            &W[(size_t)(k0 + brow) * Un + u0 + bcol]);
        As[acol + 0][arow] = a4.x;
        As[acol + 1][arow] = a4.y;
        As[acol + 2][arow] = a4.z;
        As[acol + 3][arow] = a4.w;
        *reinterpret_cast<float4*>(&Bs[brow][bcol]) = b4;
        __syncthreads();
#pragma unroll
        for (int k = 0; k < 8; k++) {
            float4 a0 = *reinterpret_cast<const float4*>(&As[k][ty * 8]);
            float4 a1 = *reinterpret_cast<const float4*>(&As[k][ty * 8 + 4]);
            float4 b0 = *reinterpret_cast<const float4*>(&Bs[k][tx * 8]);
            float4 b1 = *reinterpret_cast<const float4*>(&Bs[k][tx * 8 + 4]);
            float av[8] = {a0.x, a0.y, a0.z, a0.w, a1.x, a1.y, a1.z, a1.w};
            float bv[8] = {b0.x, b0.y, b0.z, b0.w, b1.x, b1.y, b1.z, b1.w};
#pragma unroll
            for (int i = 0; i < 8; i++)
#pragma unroll
                for (int j = 0; j < 8; j++)
                    acc[i][j] += av[i] * bv[j];
        }
        __syncthreads();
    }
#pragma unroll
    for (int i = 0; i < 8; i++) {
        float* orow = g_xw + (size_t)(m0 + ty * 8 + i) * 768 + n0 + tx * 8;
#pragma unroll
        for (int j = 0; j < 8; j++)
            orow[j] = acc[i][j] + bb[u0 + tx * 8 + j];
    }
}

// ---------------------------------------------------------------------------
// Kernel 2: recurrence. 32 clusters x 4 CTAs; 2 chains/cluster packed f32x2.
// mbarrier + st.async cross-CTA sync (no cluster.sync in the loop, L1 stays
// warm), one-step-ahead prefetch of the dep gather, xw rows and mask.
//
// smem (floats):
//   W    [3][256][64]     @0       196608 B
//   part [8][5][2][64]    @49152    20480 B
//   sv   [4][256][2]      @54272     8192 B
//   rs   [256][2]         @56320     2048 B
//   bars (2 x u64)        @56832       16 B
// ---------------------------------------------------------------------------
#define OFF_PART 49152
#define OFF_S    54272
#define OFF_RS   56320
#define OFF_BAR  56832
#define SMEM_BYTES (56836 * 4)

__global__ __launch_bounds__(256, 1) __cluster_dims__(4, 1, 1)
void rnn_seq4(const int*   __restrict__ deps,    // (T, 3)
              const int*   __restrict__ mask,    // (B, T)
              const float* __restrict__ init,    // (4, B, U)
              const float* __restrict__ Uzm, const float* __restrict__ Urm,
              const float* __restrict__ Uhm,
              float*       __restrict__ out)
{
    extern __shared__ float sm[];
    float* Ws   = sm;
    float* part = sm + OFF_PART;
    float* sv   = sm + OFF_S;
    float* rs   = sm + OFF_RS;

    const int tid  = threadIdx.x;
    const int rank = blockIdx.x & 3;
    const int cl   = blockIdx.x >> 2;
    const int b0   = cl * 2, b1 = b0 + 1;
    const int col0 = rank * NCOL;

    const uint32_t rs_bar = smem_u32(sm + OFF_BAR);
    const uint32_t st_bar = rs_bar + 8;

    // ---- weights into smem (once) ----
    for (int idx = tid; idx < 256 * NCOL; idx += 256) {
        int i = idx >> 6, j = idx & 63;
        Ws[idx]          = Urm[i * Un + col0 + j];
        Ws[16384 + idx]  = Uzm[i * Un + col0 + j];
        Ws[32768 + idx]  = Uhm[i * Un + col0 + j];
    }
    if (tid == 0) { mbar_init(rs_bar, 1); mbar_init(st_bar, 1); }

    // ---- preload initial states (t=0) ----
#pragma unroll
    for (int k = 0; k < 4; k++) {
        sv[(k * 256 + tid) * 2 + 0] = init[((size_t)k * Bn + b0) * Un + tid];
        sv[(k * 256 + tid) * 2 + 1] = init[((size_t)k * Bn + b1) * Un + tid];
    }
    // ---- preload xw/mask for t=0 (gate threads only) ----
    float xwr = 0.f, xwz = 0.f, xwh = 0.f;
    int   mreg = 0;
    const int ch = tid >> 6, jg = tid & 63;        // valid for tid<128
    const int bbg = ch ? b1 : b0;
    if (tid < 128) {
        const float* base = g_xw + ((size_t)bbg * Tn + 0) * 768;
        xwr = base[col0 + jg];
        xwz = base[256 + col0 + jg];
        xwh = base[512 + col0 + jg];
        mreg = mask[bbg * Tn + 0];
    }
    asm volatile("fence.proxy.async.shared::cta;" ::: "memory");
    __syncthreads();
    cluster_sync_();          // bars visible cluster-wide before any st.async

    const int sl = tid >> 4;          // i-slice 0..15
    const int j0 = (tid & 15) * 4;    // 4 local columns

    u64 pf[3] = {0ull, 0ull, 0ull};
    int nd[3] = {0, 0, 0};

    for (int t = 0; t < Tn; t++) {
        if (tid == 0) {
            mbar_expect_tx(rs_bar, 2048);
            mbar_expect_tx(st_bar, 2048);
        }
        if (t > 0) {
#pragma unroll
            for (int k = 0; k < 3; k++)
                *reinterpret_cast<u64*>(&sv[((k + 1) * 256 + tid) * 2]) = pf[k];
        }
        __syncthreads();

        // ---- prefetch for step t+1 (hidden under phase1/2) ----
        nd[0] = deps[t * 3 + 0];
        nd[1] = deps[t * 3 + 1];
        nd[2] = deps[t * 3 + 2];
#pragma unroll
        for (int k = 0; k < 3; k++)
            if (nd[k] < t)
                pf[k] = *reinterpret_cast<const u64*>(
                    &g_buf[(((size_t)cl * Tn + nd[k]) * Un + tid) * 2]);
        float nxr = 0.f, nxz = 0.f, nxh = 0.f;
        int nm = 0;
        if (tid < 128) {
            const int tn = (t + 1 < Tn) ? t + 1 : t;
            const float* base = g_xw + ((size_t)bbg * Tn + tn) * 768;
            nxr = base[col0 + jg];
            nxz = base[256 + col0 + jg];
            nxh = base[512 + col0 + jg];
            nm  = mask[bbg * Tn + tn];
        }

        // ---- phase 1: r preacts (4 states) + z preact, packed f32x2 ----
        u64 accR[4][4];
        u64 accZ[4];
#pragma unroll
        for (int k = 0; k < 4; k++)
#pragma unroll
            for (int c = 0; c < 4; c++) accR[k][c] = 0ull;
#pragma unroll
        for (int c = 0; c < 4; c++) accZ[c] = 0ull;

#pragma unroll
        for (int rr = 0; rr < 16; rr++) {
            const int i = (sl << 4) + rr;
            const float4 wr = *reinterpret_cast<const float4*>(&Ws[(i << 6) + j0]);
            const float4 wz = *reinterpret_cast<const float4*>(&Ws[16384 + (i << 6) + j0]);
            const u64 s0 = *reinterpret_cast<const u64*>(&sv[(0*256 + i) * 2]);
            const u64 s1 = *reinterpret_cast<const u64*>(&sv[(1*256 + i) * 2]);
            const u64 s2 = *reinterpret_cast<const u64*>(&sv[(2*256 + i) * 2]);
            const u64 s3 = *reinterpret_cast<const u64*>(&sv[(3*256 + i) * 2]);
            const u64 hp = fadd2(fadd2(s0, s1), fadd2(s2, s3));
            const u64 w0 = pack2(wr.x), w1 = pack2(wr.y),
                      w2 = pack2(wr.z), w3 = pack2(wr.w);
            const u64 z0 = pack2(wz.x), z1 = pack2(wz.y),
                      z2 = pack2(wz.z), z3 = pack2(wz.w);
            accR[0][0] = ffma2(w0, s0, accR[0][0]);
            accR[0][1] = ffma2(w1, s0, accR[0][1]);
            accR[0][2] = ffma2(w2, s0, accR[0][2]);
            accR[0][3] = ffma2(w3, s0, accR[0][3]);
            accR[1][0] = ffma2(w0, s1, accR[1][0]);
            accR[1][1] = ffma2(w1, s1, accR[1][1]);
            accR[1][2] = ffma2(w2, s1, accR[1][2]);
            accR[1][3] = ffma2(w3, s1, accR[1][3]);
            accR[2][0] = ffma2(w0, s2, accR[2][0]);
            accR[2][1] = ffma2(w1, s2, accR[2][1]);
            accR[2][2] = ffma2(w2, s2, accR[2][2]);
            accR[2][3] = ffma2(w3, s2, accR[2][3]);
            accR[3][0] = ffma2(w0, s3, accR[3][0]);
            accR[3][1] = ffma2(w1, s3, accR[3][1]);
            accR[3][2] = ffma2(w2, s3, accR[3][2]);
            accR[3][3] = ffma2(w3, s3, accR[3][3]);
            accZ[0] = ffma2(z0, hp, accZ[0]);
            accZ[1] = ffma2(z1, hp, accZ[1]);
            accZ[2] = ffma2(z2, hp, accZ[2]);
            accZ[3] = ffma2(z3, hp, accZ[3]);
        }
#pragma unroll
        for (int k = 0; k < 4; k++)
#pragma unroll
            for (int c = 0; c < 4; c++)
                accR[k][c] = fadd2(accR[k][c],
                    __shfl_xor_sync(0xffffffffu, accR[k][c], 16));
#pragma unroll
        for (int c = 0; c < 4; c++)
            accZ[c] = fadd2(accZ[c],
                __shfl_xor_sync(0xffffffffu, accZ[c], 16));
        if (!(sl & 1)) {
            const int p = sl >> 1;
#pragma unroll
            for (int g = 0; g < 4; g++) {
                float2 a0 = u2f(accR[g][0]), a1 = u2f(accR[g][1]);
                float2 a2 = u2f(accR[g][2]), a3 = u2f(accR[g][3]);
                *reinterpret_cast<float4*>(&part[((p*5+g)*2 + 0) * 64 + j0]) =
                    make_float4(a0.x, a1.x, a2.x, a3.x);
                *reinterpret_cast<float4*>(&part[((p*5+g)*2 + 1) * 64 + j0]) =
                    make_float4(a0.y, a1.y, a2.y, a3.y);
            }
            float2 c0 = u2f(accZ[0]), c1 = u2f(accZ[1]);
            float2 c2 = u2f(accZ[2]), c3 = u2f(accZ[3]);
            *reinterpret_cast<float4*>(&part[((p*5+4)*2 + 0) * 64 + j0]) =
                make_float4(c0.x, c1.x, c2.x, c3.x);
            *reinterpret_cast<float4*>(&part[((p*5+4)*2 + 1) * 64 + j0]) =
                make_float4(c0.y, c1.y, c2.y, c3.y);
        }
        __syncthreads();

        // ---- gate stage (tid<128): r,z; snapshot hsum/prev; push rs ----
        float zreg = 0.f, hsumc = 0.f, prevc = 0.f;
        if (tid < 128) {
            float pr[5] = {0.f, 0.f, 0.f, 0.f, 0.f};
#pragma unroll
            for (int p = 0; p < 8; p++)
#pragma unroll
                for (int g = 0; g < 5; g++)
                    pr[g] += part[((p*5+g)*2 + ch) * 64 + jg];
            const int col = col0 + jg;
            const float s0 = sv[(0*256 + col) * 2 + ch];
            const float s1 = sv[(1*256 + col) * 2 + ch];
            const float s2 = sv[(2*256 + col) * 2 + ch];
            const float s3 = sv[(3*256 + col) * 2 + ch];
            hsumc = s0 + s1 + s2 + s3;
            prevc = (t == 0) ? 0.f : s0;
            const float rsum = sigmoidf_(xwr + pr[0]) * s0
                             + sigmoidf_(xwr + pr[1]) * s1
                             + sigmoidf_(xwr + pr[2]) * s2
                             + sigmoidf_(xwr + pr[3]) * s3;
            zreg = sigmoidf_(xwz + pr[4]);
            const uint32_t da = smem_u32(&rs[col * 2 + ch]);
#pragma unroll
            for (int r4 = 0; r4 < 4; r4++) st_async_f32(da, rs_bar, r4, rsum);
        }
        mbar_wait(rs_bar, t & 1);

        // ---- phase 2: h_tilde preact = rs @ Uh, packed f32x2 ----
        u64 acc2[4];
#pragma unroll
        for (int c = 0; c < 4; c++) acc2[c] = 0ull;
#pragma unroll
        for (int rr = 0; rr < 16; rr++) {
            const int i = (sl << 4) + rr;
            const float4 wh = *reinterpret_cast<const float4*>(&Ws[32768 + (i << 6) + j0]);
            const u64 rp = *reinterpret_cast<const u64*>(&rs[i * 2]);
            acc2[0] = ffma2(pack2(wh.x), rp, acc2[0]);
            acc2[1] = ffma2(pack2(wh.y), rp, acc2[1]);
            acc2[2] = ffma2(pack2(wh.z), rp, acc2[2]);
            acc2[3] = ffma2(pack2(wh.w), rp, acc2[3]);
        }
#pragma unroll
        for (int c = 0; c < 4; c++)
            acc2[c] = fadd2(acc2[c],
                __shfl_xor_sync(0xffffffffu, acc2[c], 16));
        if (!(sl & 1)) {
            const int p = sl >> 1;       // reuse gate-0 slots of part
            float2 a0 = u2f(acc2[0]), a1 = u2f(acc2[1]);
            float2 a2 = u2f(acc2[2]), a3 = u2f(acc2[3]);
            *reinterpret_cast<float4*>(&part[((p*5)*2 + 0) * 64 + j0]) =
                make_float4(a0.x, a1.x, a2.x, a3.x);
            *reinterpret_cast<float4*>(&part[((p*5)*2 + 1) * 64 + j0]) =
                make_float4(a0.y, a1.y, a2.y, a3.y);
        }
        __syncthreads();

        // ---- final: h, mask, outputs, push new state ----
        if (tid < 128) {
            const int col = col0 + jg;
            float ph = 0.f;
#pragma unroll
            for (int p = 0; p < 8; p++) ph += part[((p*5)*2 + ch) * 64 + jg];
            const float ht = tanhf(xwh + ph);
            const float h  = zreg * hsumc * 0.25f + (1.f - zreg) * ht;
            const float ov = mreg ? h : 0.f;
            out[((size_t)bbg * Tn + t) * Un + col] = ov;
            const float st = mreg ? h : prevc;
            const uint32_t da = smem_u32(&sv[(0 * 256 + col) * 2 + ch]);
#pragma unroll
            for (int r4 = 0; r4 < 4; r4++) st_async_f32(da, st_bar, r4, st);
            if (t == Tn - 1) {
                out[(size_t)Bn * Tn * Un + (size_t)bbg * Un + col] = ov;
                out[(size_t)Bn * Tn * Un + (size_t)Bn * Un + (size_t)bbg * Un + col] = st;
            }
        }
        mbar_wait(st_bar, t & 1);

        // buffer row t (write-once; each CTA writes+reads its own copy path)
        *reinterpret_cast<u64*>(&g_buf[(((size_t)cl * Tn + t) * Un + tid) * 2]) =
            *reinterpret_cast<const u64*>(&sv[tid * 2]);
        // resolve deferred prefetch (dep == t -> new state just landed in sv[0])
#pragma unroll
        for (int k = 0; k < 3; k++)
            if (nd[k] >= t)
                pf[k] = *reinterpret_cast<const u64*>(&sv[tid * 2]);
        // rotate prefetched xw/mask
        xwr = nxr; xwz = nxz; xwh = nxh; mreg = nm;
    }
}

// ---------------------------------------------------------------------------
// Inputs: 0 inputs, 1 dependencies, 2 mask, 3 initial_states,
// 4 Wz, 5 Wr, 6 Wh, 7 Uz, 8 Ur, 9 Uh, 10 bz, 11 br, 12 bh
// ---------------------------------------------------------------------------
extern "C" void kernel_launch(void* const* d_in, const int* in_sizes, int n_in,
                              void* d_out, int out_size) {
    const float* X    = (const float*)d_in[0];
    const int*   deps = (const int*)  d_in[1];
    const int*   mask = (const int*)  d_in[2];
    const float* init = (const float*)d_in[3];
    const float* Wz   = (const float*)d_in[4];
    const float* Wr   = (const float*)d_in[5];
    const float* Wh   = (const float*)d_in[6];
    const float* Uz   = (const float*)d_in[7];
    const float* Ur   = (const float*)d_in[8];
    const float* Uh   = (const float*)d_in[9];
    const float* bz   = (const float*)d_in[10];
    const float* br   = (const float*)d_in[11];
    const float* bh   = (const float*)d_in[12];
    float* out = (float*)d_out;

    cudaFuncSetAttribute(rnn_seq4, cudaFuncAttributeMaxDynamicSharedMemorySize,
                         SMEM_BYTES);

    dim3 g1(256, 6);   // (32768/128, 768/128)
    xw_gemm<<<g1, 256>>>(X, Wr, Wz, Wh, br, bz, bh);
    rnn_seq4<<<128, 256, SMEM_BYTES>>>(deps, mask, init, Uz, Ur, Uh, out);
}

// round 9
// speedup vs baseline: 3.2230x; 1.0230x over previous
#include <cuda_runtime.h>
#include <math.h>
#include <stdint.h>

#define Bn 64
#define Tn 512
#define Dn 256
#define Un 256
#define NCOL 64            // output columns owned by each CTA (Un / cluster4)

// (b*T + t, [r|z|h], u) : x@W + bias, precomputed
__device__ float g_xw[(size_t)Bn * Tn * 3 * Un];
// (cluster, t, u, ch) : masked state buffer, 2 chains packed
__device__ float g_buf[(size_t)(Bn / 2) * Tn * Un * 2];

__device__ __forceinline__ float sigmoidf_(float x) {
    return 1.f / (1.f + __expf(-x));
}
__device__ __forceinline__ uint32_t smem_u32(const void* p) {
    return (uint32_t)__cvta_generic_to_shared(p);
}
__device__ __forceinline__ void cluster_sync_() {
    asm volatile("barrier.cluster.arrive.aligned;" ::: "memory");
    asm volatile("barrier.cluster.wait.aligned;"   ::: "memory");
}
__device__ __forceinline__ void mbar_init(uint32_t bar, uint32_t cnt) {
    asm volatile("mbarrier.init.shared.b64 [%0], %1;" :: "r"(bar), "r"(cnt) : "memory");
}
__device__ __forceinline__ void mbar_expect_tx(uint32_t bar, uint32_t bytes) {
    asm volatile("mbarrier.arrive.expect_tx.shared.b64 _, [%0], %1;"
                 :: "r"(bar), "r"(bytes) : "memory");
}
__device__ __forceinline__ void mbar_wait(uint32_t bar, uint32_t parity) {
    asm volatile(
        "{\n\t.reg .pred P;\n\t"
        "W_%=:\n\t"
        "mbarrier.try_wait.parity.acquire.cta.shared::cta.b64 P, [%0], %1, 0x989680;\n\t"
        "@!P bra W_%=;\n\t"
        "}" :: "r"(bar), "r"(parity) : "memory");
}
// async store of one f32 to cluster CTA `rank`'s smem, completing on its mbarrier
__device__ __forceinline__ void st_async_f32(uint32_t daddr, uint32_t baddr,
                                             int rank, float v) {
    uint32_t ra, rb;
    asm("mapa.shared::cluster.u32 %0, %1, %2;" : "=r"(ra) : "r"(daddr), "r"(rank));
    asm("mapa.shared::cluster.u32 %0, %1, %2;" : "=r"(rb) : "r"(baddr), "r"(rank));
    asm volatile(
        "st.async.shared::cluster.mbarrier::complete_tx::bytes.b32 [%0], %1, [%2];"
        :: "r"(ra), "r"(__float_as_uint(v)), "r"(rb) : "memory");
}

// ---- packed f32x2 helpers ----
typedef unsigned long long u64;
__device__ __forceinline__ u64 pack2(float a) {
    u64 r; asm("mov.b64 %0, {%1, %1};" : "=l"(r) : "f"(a)); return r;
}
__device__ __forceinline__ u64 ffma2(u64 a, u64 b, u64 c) {
    u64 d; asm("fma.rn.f32x2 %0, %1, %2, %3;" : "=l"(d) : "l"(a), "l"(b), "l"(c));
    return d;
}
__device__ __forceinline__ u64 fadd2(u64 a, u64 b) {
    u64 d; asm("add.rn.f32x2 %0, %1, %2;" : "=l"(d) : "l"(a), "l"(b));
    return d;
}
__device__ __forceinline__ float2 u2f(u64 v) {
    float2 r; asm("mov.b64 {%0, %1}, %2;" : "=f"(r.x), "=f"(r.y) : "l"(v));
    return r;
}

// ---------------------------------------------------------------------------
// Kernel 1: P = X @ [Wr | Wz | Wh] + [br | bz | bh], f32x2 microkernel.
// ---------------------------------------------------------------------------
__global__ __launch_bounds__(256) void xw_gemm(
    const float* __restrict__ X,
    const float* __restrict__ Wr, const float* __restrict__ Wz,
    const float* __restrict__ Wh,
    const float* __restrict__ br, const float* __restrict__ bz,
    const float* __restrict__ bh)
{
    __shared__ float As[8][128];
    __shared__ float Bs[8][128];
    const int tid = threadIdx.x;
    const int m0 = blockIdx.x * 128;
    const int n0 = blockIdx.y * 128;
    const int gi = n0 >> 8;
    const int u0 = n0 & 255;
    const float* __restrict__ W  = (gi == 0) ? Wr : (gi == 1 ? Wz : Wh);
    const float* __restrict__ bb = (gi == 0) ? br : (gi == 1 ? bz : bh);

    const int arow = tid >> 1;
    const int acol = (tid & 1) * 4;
    const int brow = tid >> 5;
    const int bcol = (tid & 31) * 4;
    const int ty = tid >> 4, tx = tid & 15;

    u64 acc[8][4];
#pragma unroll
    for (int i = 0; i < 8; i++)
#pragma unroll
        for (int j = 0; j < 4; j++) acc[i][j] = 0ull;

    for (int k0 = 0; k0 < Dn; k0 += 8) {
        float4 a4 = *reinterpret_cast<const float4*>(
            &X[(size_t)(m0 + arow) * Dn + k0 + acol]);
        float4 b4 = *reinterpret_cast<const float4*>(
            &W[(size_t)(k0 + brow) * Un + u0 + bcol]);
        As[acol + 0][arow] = a4.x;
        As[acol + 1][arow] = a4.y;
        As[acol + 2][arow] = a4.z;
        As[acol + 3][arow] = a4.w;
        *reinterpret_cast<float4*>(&Bs[brow][bcol]) = b4;
        __syncthreads();
#pragma unroll
        for (int k = 0; k < 8; k++) {
            float4 a0 = *reinterpret_cast<const float4*>(&As[k][ty * 8]);
            float4 a1 = *reinterpret_cast<const float4*>(&As[k][ty * 8 + 4]);
            const u64* bp = reinterpret_cast<const u64*>(&Bs[k][tx * 8]);
            const u64 b0 = bp[0], b1 = bp[1], b2 = bp[2], b3 = bp[3];
            const float av[8] = {a0.x, a0.y, a0.z, a0.w, a1.x, a1.y, a1.z, a1.w};
#pragma unroll
            for (int i = 0; i < 8; i++) {
                const u64 pa = pack2(av[i]);
                acc[i][0] = ffma2(pa, b0, acc[i][0]);
                acc[i][1] = ffma2(pa, b1, acc[i][1]);
                acc[i][2] = ffma2(pa, b2, acc[i][2]);
                acc[i][3] = ffma2(pa, b3, acc[i][3]);
            }
        }
        __syncthreads();
    }
    const u64* bbp = reinterpret_cast<const u64*>(&bb[u0 + tx * 8]);
    const u64 bias2[4] = {bbp[0], bbp[1], bbp[2], bbp[3]};
#pragma unroll
    for (int i = 0; i < 8; i++) {
        u64* orow = reinterpret_cast<u64*>(
            g_xw + (size_t)(m0 + ty * 8 + i) * 768 + n0 + tx * 8);
#pragma unroll
        for (int j = 0; j < 4; j++)
            orow[j] = fadd2(acc[i][j], bias2[j]);
    }
}

// ---------------------------------------------------------------------------
// Kernel 2: recurrence. 32 clusters x 4 CTAs; 2 chains/cluster packed f32x2.
// Phase split: phase1 = r-preacts only; Z matvec runs in the rs-delivery
// shadow; z gate folded into the final stage. hsum precomputed into smem.
//
// smem (floats):
//   W    [3][256][64]     @0       196608 B  (Ur @0, Uz @16384, Uh @32768)
//   part [8][5][2][64]    @49152    20480 B  (g0..3 = r; g4 = z; g0 reused h)
//   sv   [4][256][2]      @54272     8192 B
//   hs   [256][2]         @56320     2048 B
//   rs   [256][2]         @56832     2048 B
//   bars (2 x u64)        @57344       16 B
// ---------------------------------------------------------------------------
#define OFF_PART 49152
#define OFF_S    54272
#define OFF_HS   56320
#define OFF_RS   56832
#define OFF_BAR  57344
#define SMEM_BYTES (57348 * 4)

__global__ __launch_bounds__(256, 1) __cluster_dims__(4, 1, 1)
void rnn_seq4(const int*   __restrict__ deps,    // (T, 3)
              const int*   __restrict__ mask,    // (B, T)
              const float* __restrict__ init,    // (4, B, U)
              const float* __restrict__ Uzm, const float* __restrict__ Urm,
              const float* __restrict__ Uhm,
              float*       __restrict__ out)
{
    extern __shared__ float sm[];
    float* Ws   = sm;
    float* part = sm + OFF_PART;
    float* sv   = sm + OFF_S;
    float* hs   = sm + OFF_HS;
    float* rs   = sm + OFF_RS;

    const int tid  = threadIdx.x;
    const int rank = blockIdx.x & 3;
    const int cl   = blockIdx.x >> 2;
    const int b0   = cl * 2, b1 = b0 + 1;
    const int col0 = rank * NCOL;

    const uint32_t rs_bar = smem_u32(sm + OFF_BAR);
    const uint32_t st_bar = rs_bar + 8;

    // ---- weights into smem (once) ----
    for (int idx = tid; idx < 256 * NCOL; idx += 256) {
        int i = idx >> 6, j = idx & 63;
        Ws[idx]          = Urm[i * Un + col0 + j];
        Ws[16384 + idx]  = Uzm[i * Un + col0 + j];
        Ws[32768 + idx]  = Uhm[i * Un + col0 + j];
    }
    if (tid == 0) { mbar_init(rs_bar, 1); mbar_init(st_bar, 1); }

    // ---- preload initial states (t=0) ----
#pragma unroll
    for (int k = 0; k < 4; k++) {
        sv[(k * 256 + tid) * 2 + 0] = init[((size_t)k * Bn + b0) * Un + tid];
        sv[(k * 256 + tid) * 2 + 1] = init[((size_t)k * Bn + b1) * Un + tid];
    }
    // ---- preload xw/mask for t=0 (gate threads only) ----
    float xwr = 0.f, xwz = 0.f, xwh = 0.f;
    int   mreg = 0;
    const int ch = tid >> 6, jg = tid & 63;        // valid for tid<128
    const int bbg = ch ? b1 : b0;
    if (tid < 128) {
        const float* base = g_xw + ((size_t)bbg * Tn + 0) * 768;
        xwr = base[col0 + jg];
        xwz = base[256 + col0 + jg];
        xwh = base[512 + col0 + jg];
        mreg = mask[bbg * Tn + 0];
    }
    asm volatile("fence.proxy.async.shared::cta;" ::: "memory");
    __syncthreads();
    cluster_sync_();          // bars visible cluster-wide before any st.async

    const int sl = tid >> 4;          // i-slice 0..15
    const int j0 = (tid & 15) * 4;    // 4 local columns

    u64 pf[3] = {0ull, 0ull, 0ull};
    int nd[3] = {0, 0, 0};

    for (int t = 0; t < Tn; t++) {
        if (tid == 0) {
            mbar_expect_tx(rs_bar, 2048);
            mbar_expect_tx(st_bar, 2048);
        }
        // ---- state update + hsum (no extra barrier: per-thread data) ----
        u64 v1, v2, v3;
        if (t > 0) {
            *reinterpret_cast<u64*>(&sv[(1*256 + tid) * 2]) = pf[0];
            *reinterpret_cast<u64*>(&sv[(2*256 + tid) * 2]) = pf[1];
            *reinterpret_cast<u64*>(&sv[(3*256 + tid) * 2]) = pf[2];
            v1 = pf[0]; v2 = pf[1]; v3 = pf[2];
        } else {
            v1 = *reinterpret_cast<const u64*>(&sv[(1*256 + tid) * 2]);
            v2 = *reinterpret_cast<const u64*>(&sv[(2*256 + tid) * 2]);
            v3 = *reinterpret_cast<const u64*>(&sv[(3*256 + tid) * 2]);
        }
        const u64 v0 = *reinterpret_cast<const u64*>(&sv[tid * 2]);
        *reinterpret_cast<u64*>(&hs[tid * 2]) =
            fadd2(fadd2(v0, v1), fadd2(v2, v3));
        __syncthreads();

        // ---- prefetch for step t+1 (hidden under the phases) ----
        nd[0] = deps[t * 3 + 0];
        nd[1] = deps[t * 3 + 1];
        nd[2] = deps[t * 3 + 2];
#pragma unroll
        for (int k = 0; k < 3; k++)
            if (nd[k] < t)
                pf[k] = *reinterpret_cast<const u64*>(
                    &g_buf[(((size_t)cl * Tn + nd[k]) * Un + tid) * 2]);
        float nxr = 0.f, nxz = 0.f, nxh = 0.f;
        int nm = 0;
        if (tid < 128) {
            const int tn = (t + 1 < Tn) ? t + 1 : t;
            const float* base = g_xw + ((size_t)bbg * Tn + tn) * 768;
            nxr = base[col0 + jg];
            nxz = base[256 + col0 + jg];
            nxh = base[512 + col0 + jg];
            nm  = mask[bbg * Tn + tn];
        }

        // ---- phase 1: r preacts only (4 states), packed f32x2 ----
        u64 aR[4][4];
#pragma unroll
        for (int k = 0; k < 4; k++)
#pragma unroll
            for (int c = 0; c < 4; c++) aR[k][c] = 0ull;
#pragma unroll
        for (int rr = 0; rr < 16; rr++) {
            const int i = (sl << 4) + rr;
            const float4 wr = *reinterpret_cast<const float4*>(&Ws[(i << 6) + j0]);
            const u64 s0 = *reinterpret_cast<const u64*>(&sv[(0*256 + i) * 2]);
            const u64 s1 = *reinterpret_cast<const u64*>(&sv[(1*256 + i) * 2]);
            const u64 s2 = *reinterpret_cast<const u64*>(&sv[(2*256 + i) * 2]);
            const u64 s3 = *reinterpret_cast<const u64*>(&sv[(3*256 + i) * 2]);
            const u64 w0 = pack2(wr.x), w1 = pack2(wr.y),
                      w2 = pack2(wr.z), w3 = pack2(wr.w);
            aR[0][0] = ffma2(w0, s0, aR[0][0]);
            aR[0][1] = ffma2(w1, s0, aR[0][1]);
            aR[0][2] = ffma2(w2, s0, aR[0][2]);
            aR[0][3] = ffma2(w3, s0, aR[0][3]);
            aR[1][0] = ffma2(w0, s1, aR[1][0]);
            aR[1][1] = ffma2(w1, s1, aR[1][1]);
            aR[1][2] = ffma2(w2, s1, aR[1][2]);
            aR[1][3] = ffma2(w3, s1, aR[1][3]);
            aR[2][0] = ffma2(w0, s2, aR[2][0]);
            aR[2][1] = ffma2(w1, s2, aR[2][1]);
            aR[2][2] = ffma2(w2, s2, aR[2][2]);
            aR[2][3] = ffma2(w3, s2, aR[2][3]);
            aR[3][0] = ffma2(w0, s3, aR[3][0]);
            aR[3][1] = ffma2(w1, s3, aR[3][1]);
            aR[3][2] = ffma2(w2, s3, aR[3][2]);
            aR[3][3] = ffma2(w3, s3, aR[3][3]);
        }
#pragma unroll
        for (int k = 0; k < 4; k++)
#pragma unroll
            for (int c = 0; c < 4; c++)
                aR[k][c] = fadd2(aR[k][c],
                    __shfl_xor_sync(0xffffffffu, aR[k][c], 16));
        if (!(sl & 1)) {
            const int p = sl >> 1;
#pragma unroll
            for (int g = 0; g < 4; g++) {
                float2 a0 = u2f(aR[g][0]), a1 = u2f(aR[g][1]);
                float2 a2 = u2f(aR[g][2]), a3 = u2f(aR[g][3]);
                *reinterpret_cast<float4*>(&part[((p*5+g)*2 + 0) * 64 + j0]) =
                    make_float4(a0.x, a1.x, a2.x, a3.x);
                *reinterpret_cast<float4*>(&part[((p*5+g)*2 + 1) * 64 + j0]) =
                    make_float4(a0.y, a1.y, a2.y, a3.y);
            }
        }
        __syncthreads();

        // ---- gate stage (tid<128): r gates, rsum; snapshot hsum/prev ----
        float hsumc = 0.f, prevc = 0.f;
        if (tid < 128) {
            float pr[4] = {0.f, 0.f, 0.f, 0.f};
#pragma unroll
            for (int p = 0; p < 8; p++)
#pragma unroll
                for (int g = 0; g < 4; g++)
                    pr[g] += part[((p*5+g)*2 + ch) * 64 + jg];
            const int col = col0 + jg;
            const float s0 = sv[(0*256 + col) * 2 + ch];
            const float s1 = sv[(1*256 + col) * 2 + ch];
            const float s2 = sv[(2*256 + col) * 2 + ch];
            const float s3 = sv[(3*256 + col) * 2 + ch];
            hsumc = s0 + s1 + s2 + s3;
            prevc = (t == 0) ? 0.f : s0;
            const float rsum = sigmoidf_(xwr + pr[0]) * s0
                             + sigmoidf_(xwr + pr[1]) * s1
                             + sigmoidf_(xwr + pr[2]) * s2
                             + sigmoidf_(xwr + pr[3]) * s3;
            const uint32_t da = smem_u32(&rs[col * 2 + ch]);
#pragma unroll
            for (int r4 = 0; r4 < 4; r4++) st_async_f32(da, rs_bar, r4, rsum);
        }

        // ---- Z matvec (all threads) — hides rs delivery latency ----
        u64 aZ[4];
#pragma unroll
        for (int c = 0; c < 4; c++) aZ[c] = 0ull;
#pragma unroll
        for (int rr = 0; rr < 16; rr++) {
            const int i = (sl << 4) + rr;
            const float4 wz = *reinterpret_cast<const float4*>(&Ws[16384 + (i << 6) + j0]);
            const u64 hp = *reinterpret_cast<const u64*>(&hs[i * 2]);
            aZ[0] = ffma2(pack2(wz.x), hp, aZ[0]);
            aZ[1] = ffma2(pack2(wz.y), hp, aZ[1]);
            aZ[2] = ffma2(pack2(wz.z), hp, aZ[2]);
            aZ[3] = ffma2(pack2(wz.w), hp, aZ[3]);
        }
#pragma unroll
        for (int c = 0; c < 4; c++)
            aZ[c] = fadd2(aZ[c],
                __shfl_xor_sync(0xffffffffu, aZ[c], 16));
        if (!(sl & 1)) {
            const int p = sl >> 1;
            float2 c0 = u2f(aZ[0]), c1 = u2f(aZ[1]);
            float2 c2 = u2f(aZ[2]), c3 = u2f(aZ[3]);
            *reinterpret_cast<float4*>(&part[((p*5+4)*2 + 0) * 64 + j0]) =
                make_float4(c0.x, c1.x, c2.x, c3.x);
            *reinterpret_cast<float4*>(&part[((p*5+4)*2 + 1) * 64 + j0]) =
                make_float4(c0.y, c1.y, c2.y, c3.y);
        }
        mbar_wait(rs_bar, t & 1);

        // ---- phase 2: h_tilde preact = rs @ Uh, packed f32x2 ----
        u64 a2[4];
#pragma unroll
        for (int c = 0; c < 4; c++) a2[c] = 0ull;
#pragma unroll
        for (int rr = 0; rr < 16; rr++) {
            const int i = (sl << 4) + rr;
            const float4 wh = *reinterpret_cast<const float4*>(&Ws[32768 + (i << 6) + j0]);
            const u64 rp = *reinterpret_cast<const u64*>(&rs[i * 2]);
            a2[0] = ffma2(pack2(wh.x), rp, a2[0]);
            a2[1] = ffma2(pack2(wh.y), rp, a2[1]);
            a2[2] = ffma2(pack2(wh.z), rp, a2[2]);
            a2[3] = ffma2(pack2(wh.w), rp, a2[3]);
        }
#pragma unroll
        for (int c = 0; c < 4; c++)
            a2[c] = fadd2(a2[c],
                __shfl_xor_sync(0xffffffffu, a2[c], 16));
        if (!(sl & 1)) {
            const int p = sl >> 1;       // reuse gate-0 slots of part
            float2 a0 = u2f(a2[0]), a1 = u2f(a2[1]);
            float2 b2 = u2f(a2[2]), b3 = u2f(a2[3]);
            *reinterpret_cast<float4*>(&part[((p*5)*2 + 0) * 64 + j0]) =
                make_float4(a0.x, a1.x, b2.x, b3.x);
            *reinterpret_cast<float4*>(&part[((p*5)*2 + 1) * 64 + j0]) =
                make_float4(a0.y, a1.y, b2.y, b3.y);
        }
        __syncthreads();

        // ---- final: z, h, mask, outputs, push new state ----
        if (tid < 128) {
            const int col = col0 + jg;
            float ph = 0.f, pz = 0.f;
#pragma unroll
            for (int p = 0; p < 8; p++) {
                ph += part[((p*5+0)*2 + ch) * 64 + jg];
                pz += part[((p*5+4)*2 + ch) * 64 + jg];
            }
            const float z  = sigmoidf_(xwz + pz);
            const float ht = 2.f * sigmoidf_(2.f * (xwh + ph)) - 1.f;  // tanh
            const float h  = z * hsumc * 0.25f + (1.f - z) * ht;
            const float ov = mreg ? h : 0.f;
            out[((size_t)bbg * Tn + t) * Un + col] = ov;
            const float st = mreg ? h : prevc;
            const uint32_t da = smem_u32(&sv[(0 * 256 + col) * 2 + ch]);
#pragma unroll
            for (int r4 = 0; r4 < 4; r4++) st_async_f32(da, st_bar, r4, st);
            if (t == Tn - 1) {
                out[(size_t)Bn * Tn * Un + (size_t)bbg * Un + col] = ov;
                out[(size_t)Bn * Tn * Un + (size_t)Bn * Un + (size_t)bbg * Un + col] = st;
            }
        }
        mbar_wait(st_bar, t & 1);

        // buffer row t (write-once; same thread re-reads its own element)
        *reinterpret_cast<u64*>(&g_buf[(((size_t)cl * Tn + t) * Un + tid) * 2]) =
            *reinterpret_cast<const u64*>(&sv[tid * 2]);
        // resolve deferred prefetch (dep == t -> new state just landed)
#pragma unroll
        for (int k = 0; k < 3; k++)
            if (nd[k] >= t)
                pf[k] = *reinterpret_cast<const u64*>(&sv[tid * 2]);
        // rotate prefetched xw/mask
        xwr = nxr; xwz = nxz; xwh = nxh; mreg = nm;
    }
}

// ---------------------------------------------------------------------------
// Inputs: 0 inputs, 1 dependencies, 2 mask, 3 initial_states,
// 4 Wz, 5 Wr, 6 Wh, 7 Uz, 8 Ur, 9 Uh, 10 bz, 11 br, 12 bh
// ---------------------------------------------------------------------------
extern "C" void kernel_launch(void* const* d_in, const int* in_sizes, int n_in,
                              void* d_out, int out_size) {
    const float* X    = (const float*)d_in[0];
    const int*   deps = (const int*)  d_in[1];
    const int*   mask = (const int*)  d_in[2];
    const float* init = (const float*)d_in[3];
    const float* Wz   = (const float*)d_in[4];
    const float* Wr   = (const float*)d_in[5];
    const float* Wh   = (const float*)d_in[6];
    const float* Uz   = (const float*)d_in[7];
    const float* Ur   = (const float*)d_in[8];
    const float* Uh   = (const float*)d_in[9];
    const float* bz   = (const float*)d_in[10];
    const float* br   = (const float*)d_in[11];
    const float* bh   = (const float*)d_in[12];
    float* out = (float*)d_out;

    cudaFuncSetAttribute(rnn_seq4, cudaFuncAttributeMaxDynamicSharedMemorySize,
                         SMEM_BYTES);

    dim3 g1(256, 6);   // (32768/128, 768/128)
    xw_gemm<<<g1, 256>>>(X, Wr, Wz, Wh, br, bz, bh);
    rnn_seq4<<<128, 256, SMEM_BYTES>>>(deps, mask, init, Uz, Ur, Uh, out);
}